// round 5
// baseline (speedup 1.0000x reference)
#include <cuda_runtime.h>
#include <math.h>

// QuantumPoolingLayer R5: fused, self-contained blocks at 256 KiB granularity.
// Unit = (mc: 16 m-values, b): block reads all 64x64 spatial for its 16 m,
// reduces 4 quadrants, sims 16 samples, writes out. 2048 blocks, no scratch,
// no atomics, no fences. Straggle ~ 1/2 block duration only.

#define NQ 4

struct c32 { float x, y; };
__device__ __forceinline__ c32 cadd(c32 a, c32 b){ return {a.x+b.x, a.y+b.y}; }
__device__ __forceinline__ c32 cmul(c32 a, c32 b){
    return { fmaf(a.x, b.x, -a.y*b.y), fmaf(a.x, b.y, a.y*b.x) };
}

// x[4] = tanh-normalized pooled values, w -> 24 floats [layer][qubit][phi,th,om].
__device__ __forceinline__ float simulate_sample(const float x[4], const float* __restrict__ w)
{
    c32 s[16];
#pragma unroll
    for (int k = 0; k < 16; k++) s[k] = {0.f, 0.f};
    s[0].x = 1.f;

    // Initial RY(x*pi); wire q <-> bit (3-q) => mask = 8>>q.
#pragma unroll
    for (int q = 0; q < NQ; q++) {
        float half = x[q] * 1.57079632679489662f;
        float sn, cs; __sincosf(half, &sn, &cs);
        const int m = 8 >> q;
#pragma unroll
        for (int k = 0; k < 16; k++) {
            if (!(k & m)) {
                c32 v0 = s[k], v1 = s[k | m];
                s[k]     = { cs*v0.x - sn*v1.x, cs*v0.y - sn*v1.y };
                s[k | m] = { sn*v0.x + cs*v1.x, sn*v0.y + cs*v1.y };
            }
        }
    }

#pragma unroll
    for (int layer = 0; layer < 2; layer++) {
#pragma unroll
        for (int q = 0; q < NQ; q++) {
            const float* g = w + (layer * 4 + q) * 3;
            float phi = g[0], th = g[1], om = g[2];
            float stt, ctt; __sincosf(0.5f * th, &stt, &ctt);
            float sa, ca;  __sincosf(0.5f * (phi + om), &sa, &ca);
            float sb, cb;  __sincosf(0.5f * (phi - om), &sb, &cb);
            c32 U00 = { ctt * ca, -ctt * sa };
            c32 U01 = { -stt * cb, -stt * sb };
            c32 U10 = { stt * cb, -stt * sb };
            c32 U11 = { ctt * ca,  ctt * sa };
            const int m = 8 >> q;
#pragma unroll
            for (int k = 0; k < 16; k++) {
                if (!(k & m)) {
                    c32 v0 = s[k], v1 = s[k | m];
                    c32 n0 = cadd(cmul(U00, v0), cmul(U01, v1));
                    c32 n1 = cadd(cmul(U10, v0), cmul(U11, v1));
                    s[k] = n0; s[k | m] = n1;
                }
            }
        }
        // CNOT(c,t) for all c<t in order: amplitude swaps.
#pragma unroll
        for (int c = 0; c < NQ; c++) {
#pragma unroll
            for (int t = c + 1; t < NQ; t++) {
                const int cm = 8 >> c, tm = 8 >> t;
#pragma unroll
                for (int k = 0; k < 16; k++) {
                    if ((k & cm) && !(k & tm)) {
                        c32 tmp = s[k]; s[k] = s[k | tm]; s[k | tm] = tmp;
                    }
                }
            }
        }
    }

    float p = 0.f;
#pragma unroll
    for (int k = 0; k < 16; k++) {
        float pr = fmaf(s[k].x, s[k].x, s[k].y * s[k].y);
        p += (k < 8) ? pr : -pr;
    }
    return p;
}

// Grid (mc=32, b=64), 512 threads, 2 blocks/SM (64 regs for 8 loads in flight).
// Thread: lane = tid&3 (float4 -> 4 of the block's 16 m), g = tid>>2 in 0..127:
// row = g&63, colhalf = g>>6. Sums its col half's 32 j values -> one quadrant
// partial (quadrant = (row>=32, colhalf)) for 4 m values.
__global__ void __launch_bounds__(512, 2)
qpl_kernel(const float* __restrict__ in, const float* __restrict__ w, float* __restrict__ out)
{
    const int mc = blockIdx.x;           // 16-m chunk: m in [mc*16, mc*16+16)
    const int b  = blockIdx.y;
    const int tid  = threadIdx.x;
    const int lane = tid & 3;            // m_local = lane*4 .. +3
    const int g    = tid >> 2;           // 0..127
    const int row  = g & 63;
    const int ch   = g >> 6;             // col half

    const float* base = in
        + (((size_t)b * 64 + row) * 64 + ch * 32) * 512
        + mc * 16 + (lane << 2);

    float4 a = {0.f, 0.f, 0.f, 0.f};
#pragma unroll
    for (int j0 = 0; j0 < 32; j0 += 8) {
        float4 v[8];
#pragma unroll
        for (int k = 0; k < 8; k++)
            v[k] = __ldcs(reinterpret_cast<const float4*>(base + (size_t)(j0 + k) * 512));
#pragma unroll
        for (int k = 0; k < 8; k++) {
            a.x += v[k].x; a.y += v[k].y; a.z += v[k].z; a.w += v[k].w;
        }
    }

    __shared__ float4 part[2][64][4];    // [colhalf][row][lane], 8 KB
    __shared__ float  quads[4][16];      // [quad][m_local]
    part[ch][row][lane] = a;
    __syncthreads();

    if (tid < 64) {
        // quad = (rowhalf, colhalf); each thread reduces 32 rows for one m.
        const int quad = tid >> 4;       // 0..3
        const int rh   = quad >> 1;
        const int c2   = quad & 1;
        const int ml   = tid & 15;       // m_local
        const float* pf = (const float*)part;
        float ssum = 0.f;
#pragma unroll
        for (int r = 0; r < 32; r++)
            ssum += pf[(c2 * 64 + rh * 32 + r) * 16 + ml];
        quads[rh * 2 + c2][ml] = ssum;
    }
    __syncthreads();

    if (tid < 16) {
        float x[4];
#pragma unroll
        for (int q = 0; q < 4; q++)
            x[q] = tanhf(quads[q][tid] * (1.0f / 1024.0f));
        // mm = mc*16 + tid; widx = b*8 + (mm>>6) = b*8 + (mc>>2) (uniform)
        const float* wp = w + (size_t)(b * 8 + (mc >> 2)) * 24;
        out[b * 512 + mc * 16 + tid] = simulate_sample(x, wp);
    }
}

extern "C" void kernel_launch(void* const* d_in, const int* in_sizes, int n_in,
                              void* d_out, int out_size)
{
    const float* in = (const float*)d_in[0];
    const float* w  = (const float*)d_in[1];
    if (n_in >= 2 && in_sizes[0] < in_sizes[1]) {   // defensive: identify by size
        in = (const float*)d_in[1];
        w  = (const float*)d_in[0];
    }
    dim3 grid(32, 64);
    qpl_kernel<<<grid, 512>>>(in, w, (float*)d_out);
}